// round 1
// baseline (speedup 1.0000x reference)
#include <cuda_runtime.h>

// ---------------- problem constants ----------------
constexpr int kB   = 4;
constexpr int kL   = 1024;
constexpr int kDim = 256;
constexpr int kDI  = 512;   // d_inner
constexpr int kDS  = 64;    // d_state
constexpr int kDTR = 16;    // dt_rank
constexpr int kM   = kB * kL;  // 4096 rows

// ---------------- scratch (device globals; no allocs allowed) ----------------
__device__ float g_xn [kM * kDim];          // layernormed x
__device__ float g_xz [kM * 2 * kDI];       // [u_pre | z]
__device__ float g_u  [kM * kDI];           // conv+silu output
__device__ float g_sz [kM * kDI];           // silu(z), precomputed
__device__ float g_dbl[4 * kM * 80];        // split-K slabs of u @ W_x^T
__device__ float g_dt [kM * kDI];           // softplus dt
__device__ float g_Bs [kM * kDS];           // B_t
__device__ float g_y  [kM * kDI];           // scan output (epilogue fused)

__device__ __forceinline__ float ex2f(float x) {
    float r; asm("ex2.approx.f32 %0, %1;" : "=f"(r) : "f"(x)); return r;
}
__device__ __forceinline__ float sigmoidf_(float x) {
    return 1.f / (1.f + __expf(-x));
}

// ---------------- LayerNorm: one block per row ----------------
__global__ void ln_kernel(const float* __restrict__ x,
                          const float* __restrict__ gamma,
                          const float* __restrict__ beta) {
    int row = blockIdx.x, t = threadIdx.x;           // 256 threads
    float v = x[row * kDim + t];
    float s = v, s2 = v * v;
    #pragma unroll
    for (int o = 16; o > 0; o >>= 1) {
        s  += __shfl_xor_sync(0xffffffffu, s,  o);
        s2 += __shfl_xor_sync(0xffffffffu, s2, o);
    }
    __shared__ float sh[16];
    if ((t & 31) == 0) { sh[t >> 5] = s; sh[8 + (t >> 5)] = s2; }
    __syncthreads();
    float ms = 0.f, ms2 = 0.f;
    #pragma unroll
    for (int i = 0; i < 8; i++) { ms += sh[i]; ms2 += sh[8 + i]; }
    float mu  = ms * (1.f / kDim);
    float var = ms2 * (1.f / kDim) - mu * mu;
    float r = rsqrtf(var + 1e-5f);
    g_xn[row * kDim + t] = (v - mu) * r * gamma[t] + beta[t];
}

// ---------------- generic NT SGEMM: C[M,N] = A[M,K] * B[N,K]^T ----------------
// Optional split-K: blockIdx.z selects a K-chunk of length klen; each chunk
// writes its own slab C + z*M*N.
template<int BM, int BN, int BK, int TM, int TN>
__global__ void __launch_bounds__((BM/TM)*(BN/TN))
sgemm_nt(int M, int N, int K, int klen,
         const float* __restrict__ A, const float* __restrict__ B,
         float* __restrict__ Cout) {
    constexpr int THREADS = (BM / TM) * (BN / TN);
    __shared__ float As[BK][BM];
    __shared__ float Bs[BK][BN];
    int tid = threadIdx.x;
    int bn = blockIdx.x * BN;
    int bm = blockIdx.y * BM;
    int kz = blockIdx.z;
    const float* Ap = A + (size_t)bm * K + kz * klen;
    const float* Bp = B + (size_t)bn * K + kz * klen;
    float* Cp = Cout + (size_t)kz * M * N;

    float acc[TM][TN];
    #pragma unroll
    for (int i = 0; i < TM; i++)
        #pragma unroll
        for (int j = 0; j < TN; j++) acc[i][j] = 0.f;

    int tx = tid % (BN / TN);
    int ty = tid / (BN / TN);

    for (int k0 = 0; k0 < klen; k0 += BK) {
        #pragma unroll
        for (int i = 0; i < BM * BK / THREADS; i++) {
            int idx = tid + i * THREADS;
            int r = idx / BK, c = idx % BK;
            As[c][r] = Ap[r * K + k0 + c];
        }
        #pragma unroll
        for (int i = 0; i < BN * BK / THREADS; i++) {
            int idx = tid + i * THREADS;
            int r = idx / BK, c = idx % BK;
            Bs[c][r] = Bp[r * K + k0 + c];
        }
        __syncthreads();
        #pragma unroll
        for (int k = 0; k < BK; k++) {
            float a[TM], bq[TN];
            #pragma unroll
            for (int i = 0; i < TM; i++) a[i] = As[k][ty * TM + i];
            #pragma unroll
            for (int j = 0; j < TN; j++) bq[j] = Bs[k][tx * TN + j];
            #pragma unroll
            for (int i = 0; i < TM; i++)
                #pragma unroll
                for (int j = 0; j < TN; j++)
                    acc[i][j] = fmaf(a[i], bq[j], acc[i][j]);
        }
        __syncthreads();
    }
    #pragma unroll
    for (int i = 0; i < TM; i++)
        #pragma unroll
        for (int j = 0; j < TN; j++)
            Cp[(size_t)(bm + ty * TM + i) * N + bn + tx * TN + j] = acc[i][j];
}

// ---------------- causal depthwise conv (k=4) + SiLU; also silu(z) ----------------
__global__ void conv_silu_kernel(const float* __restrict__ cw,
                                 const float* __restrict__ cb) {
    int bl = blockIdx.x;              // b*1024 + l
    int d  = threadIdx.x;             // 512 threads
    int l  = bl & 1023;
    float w0 = cw[d*4+0], w1 = cw[d*4+1], w2 = cw[d*4+2], w3 = cw[d*4+3];
    const float* base = g_xz + (size_t)(bl - l) * 1024 + d;   // start of this batch
    float acc = cb[d];
    acc = fmaf(w3, base[(size_t)l * 1024], acc);
    if (l >= 1) acc = fmaf(w2, base[(size_t)(l-1) * 1024], acc);
    if (l >= 2) acc = fmaf(w1, base[(size_t)(l-2) * 1024], acc);
    if (l >= 3) acc = fmaf(w0, base[(size_t)(l-3) * 1024], acc);
    float uu = acc * sigmoidf_(acc);
    g_u[(size_t)bl * kDI + d] = uu;
    float z = g_xz[(size_t)bl * 1024 + kDI + d];
    g_sz[(size_t)bl * kDI + d] = z * sigmoidf_(z);
}

// ---------------- dt = softplus(dbl[:, :16] @ W_dt^T + b_dt); extract Bs ----------------
// Block handles 16 rows. Sums the 4 split-K slabs of g_dbl.
__global__ void dt_kernel(const float* __restrict__ Wdt,
                          const float* __restrict__ bdt) {
    int m0 = blockIdx.x * 16;
    int tid = threadIdx.x;            // 256 threads
    __shared__ float s16[16][16];
    for (int i = tid; i < 16 * 80; i += 256) {
        int r = i / 80, c = i % 80;
        int idx = (m0 + r) * 80 + c;
        float v = g_dbl[idx] + g_dbl[kM*80 + idx]
                + g_dbl[2*kM*80 + idx] + g_dbl[3*kM*80 + idx];
        if (c < 16) s16[r][c] = v;
        else        g_Bs[(size_t)(m0 + r) * kDS + (c - 16)] = v;
    }
    __syncthreads();
    #pragma unroll
    for (int dd = 0; dd < 2; dd++) {
        int d = tid + dd * 256;
        float w[16];
        const float4* wp = (const float4*)(Wdt + d * 16);
        #pragma unroll
        for (int q = 0; q < 4; q++) {
            float4 f = wp[q];
            w[4*q] = f.x; w[4*q+1] = f.y; w[4*q+2] = f.z; w[4*q+3] = f.w;
        }
        float bb = bdt[d];
        #pragma unroll 4
        for (int r = 0; r < 16; r++) {
            float acc = bb;
            #pragma unroll
            for (int q = 0; q < 16; q++) acc = fmaf(s16[r][q], w[q], acc);
            float o = (acc > 20.f) ? acc : log1pf(__expf(acc));
            g_dt[(size_t)(m0 + r) * kDI + d] = o;
        }
    }
}

// ---------------- selective scan ----------------
// One warp per (b, d) channel; lane j holds states n=2j, n=2j+1.
// Epilogue (y + u*D) * silu(z) fused; writes g_y.
__global__ void __launch_bounds__(512)
scan_kernel(const float* __restrict__ C_SA,
            const float* __restrict__ A_log,
            const float* __restrict__ Dp) {
    int b    = blockIdx.y;
    int wid  = threadIdx.x >> 5;
    int lane = threadIdx.x & 31;
    int d    = blockIdx.x * 16 + wid;
    const float L2E = 1.4426950408889634f;
    float a0 = -__expf(A_log[d * kDS + 2 * lane])     * L2E;  // A*log2(e)
    float a1 = -__expf(A_log[d * kDS + 2 * lane + 1]) * L2E;
    float Dd = Dp[d];
    float h0 = 0.f, h1 = 0.f;

    const float*  dtp = g_dt + (size_t)b * kL * kDI + d;
    const float*  up  = g_u  + (size_t)b * kL * kDI + d;
    const float*  szp = g_sz + (size_t)b * kL * kDI + d;
    float*        yp  = g_y  + (size_t)b * kL * kDI + d;
    const float2* Bp  = (const float2*)(g_Bs + (size_t)b * kL * kDS) + lane;
    const float2* Cp  = (const float2*)(C_SA + (size_t)b * kL * kDS) + lane;

    #pragma unroll 2
    for (int l = 0; l < kL; l++) {
        float  dt = __ldg(dtp);
        float  u  = __ldg(up);
        float2 Bv = __ldg(Bp);
        float2 Cv = __ldg(Cp);
        float dA0 = ex2f(dt * a0);
        float dA1 = ex2f(dt * a1);
        float x = dt * u;
        h0 = fmaf(dA0, h0, x * Bv.x);
        h1 = fmaf(dA1, h1, x * Bv.y);
        float p = fmaf(h0, Cv.x, h1 * Cv.y);
        #pragma unroll
        for (int o = 16; o > 0; o >>= 1)
            p += __shfl_xor_sync(0xffffffffu, p, o);
        if (lane == 0)
            *yp = (p + u * Dd) * __ldg(szp);
        dtp += kDI; up += kDI; szp += kDI; yp += kDI; Bp += 32; Cp += 32;
    }
}

// ---------------- launch ----------------
extern "C" void kernel_launch(void* const* d_in, const int* in_sizes, int n_in,
                              void* d_out, int out_size) {
    const float* x      = (const float*)d_in[0];
    const float* C_SA   = (const float*)d_in[1];
    const float* gamma  = (const float*)d_in[2];
    const float* beta   = (const float*)d_in[3];
    const float* W_in   = (const float*)d_in[4];
    const float* conv_w = (const float*)d_in[5];
    const float* conv_b = (const float*)d_in[6];
    const float* W_x    = (const float*)d_in[7];
    const float* W_dt   = (const float*)d_in[8];
    const float* b_dt   = (const float*)d_in[9];
    const float* A_log  = (const float*)d_in[10];
    const float* Dv     = (const float*)d_in[11];
    const float* W_out  = (const float*)d_in[12];
    float* out = (float*)d_out;

    float *p_xn, *p_xz, *p_u, *p_dbl, *p_y;
    cudaGetSymbolAddress((void**)&p_xn,  g_xn);
    cudaGetSymbolAddress((void**)&p_xz,  g_xz);
    cudaGetSymbolAddress((void**)&p_u,   g_u);
    cudaGetSymbolAddress((void**)&p_dbl, g_dbl);
    cudaGetSymbolAddress((void**)&p_y,   g_y);

    // 1. LayerNorm
    ln_kernel<<<kM, kDim>>>(x, gamma, beta);
    // 2. xz = xn @ W_in^T   (4096 x 1024 x 256)
    sgemm_nt<128, 64, 8, 8, 4><<<dim3(1024 / 64, kM / 128, 1), 256>>>(
        kM, 1024, kDim, kDim, p_xn, W_in, p_xz);
    // 3. causal conv + SiLU, plus silu(z)
    conv_silu_kernel<<<kM, kDI>>>(conv_w, conv_b);
    // 4. dbl = u @ W_x^T   (4096 x 80 x 512), split-K x4 into slabs
    sgemm_nt<64, 80, 16, 4, 5><<<dim3(1, kM / 64, 4), 256>>>(
        kM, 80, kDI, kDI / 4, p_u, W_x, p_dbl);
    // 5. dt = softplus(...), Bs extraction (sums slabs)
    dt_kernel<<<kM / 16, 256>>>(W_dt, b_dt);
    // 6. selective scan (fused + u*D, * silu(z))
    scan_kernel<<<dim3(kDI / 16, kB), 512>>>(C_SA, A_log, Dv);
    // 7. out = y @ W_out^T  (4096 x 256 x 512)
    sgemm_nt<128, 64, 8, 8, 4><<<dim3(kDim / 64, kM / 128, 1), 256>>>(
        kM, kDim, kDI, kDI, p_y, W_out, out);
}

// round 2
// speedup vs baseline: 1.1481x; 1.1481x over previous
#include <cuda_runtime.h>

// ---------------- problem constants ----------------
constexpr int kB   = 4;
constexpr int kL   = 1024;
constexpr int kDim = 256;
constexpr int kDI  = 512;   // d_inner
constexpr int kDS  = 64;    // d_state
constexpr int kM   = kB * kL;  // 4096 rows
constexpr int kSlabs = 8;      // split-K slabs for GEMM2

// ---------------- scratch (device globals; no allocs allowed) ----------------
__device__ float g_xn [kM * kDim];            // layernormed x
__device__ float g_xz [kM * 2 * kDI];         // [u_pre | z]
__device__ float g_u  [kM * kDI];             // conv+silu output
__device__ float g_sz [kM * kDI];             // silu(z), precomputed
__device__ float g_dbl[kSlabs * kM * 80];     // split-K slabs of u @ W_x^T
__device__ float g_dt [kM * kDI];             // softplus dt
__device__ float g_Bs [kM * kDS];             // B_t
__device__ float g_y  [kM * kDI];             // scan output (epilogue fused)

__device__ __forceinline__ float ex2f(float x) {
    float r; asm("ex2.approx.f32 %0, %1;" : "=f"(r) : "f"(x)); return r;
}
__device__ __forceinline__ float sigmoidf_(float x) {
    return 1.f / (1.f + __expf(-x));
}

// ---------------- LayerNorm: one block per row ----------------
__global__ void ln_kernel(const float* __restrict__ x,
                          const float* __restrict__ gamma,
                          const float* __restrict__ beta) {
    int row = blockIdx.x, t = threadIdx.x;           // 256 threads
    float v = x[row * kDim + t];
    float s = v, s2 = v * v;
    #pragma unroll
    for (int o = 16; o > 0; o >>= 1) {
        s  += __shfl_xor_sync(0xffffffffu, s,  o);
        s2 += __shfl_xor_sync(0xffffffffu, s2, o);
    }
    __shared__ float sh[16];
    if ((t & 31) == 0) { sh[t >> 5] = s; sh[8 + (t >> 5)] = s2; }
    __syncthreads();
    float ms = 0.f, ms2 = 0.f;
    #pragma unroll
    for (int i = 0; i < 8; i++) { ms += sh[i]; ms2 += sh[8 + i]; }
    float mu  = ms * (1.f / kDim);
    float var = ms2 * (1.f / kDim) - mu * mu;
    float r = rsqrtf(var + 1e-5f);
    g_xn[row * kDim + t] = (v - mu) * r * gamma[t] + beta[t];
}

// ---------------- generic NT SGEMM: C[M,N] = A[M,K] * B[N,K]^T ----------------
template<int BM, int BN, int BK, int TM, int TN>
__global__ void __launch_bounds__((BM/TM)*(BN/TN))
sgemm_nt(int M, int N, int K, int klen,
         const float* __restrict__ A, const float* __restrict__ B,
         float* __restrict__ Cout) {
    constexpr int THREADS = (BM / TM) * (BN / TN);
    __shared__ float As[BK][BM];
    __shared__ float Bs[BK][BN];
    int tid = threadIdx.x;
    int bn = blockIdx.x * BN;
    int bm = blockIdx.y * BM;
    int kz = blockIdx.z;
    const float* Ap = A + (size_t)bm * K + kz * klen;
    const float* Bp = B + (size_t)bn * K + kz * klen;
    float* Cp = Cout + (size_t)kz * M * N;

    float acc[TM][TN];
    #pragma unroll
    for (int i = 0; i < TM; i++)
        #pragma unroll
        for (int j = 0; j < TN; j++) acc[i][j] = 0.f;

    int tx = tid % (BN / TN);
    int ty = tid / (BN / TN);

    for (int k0 = 0; k0 < klen; k0 += BK) {
        #pragma unroll
        for (int i = 0; i < BM * BK / THREADS; i++) {
            int idx = tid + i * THREADS;
            int r = idx / BK, c = idx % BK;
            As[c][r] = Ap[r * K + k0 + c];
        }
        #pragma unroll
        for (int i = 0; i < BN * BK / THREADS; i++) {
            int idx = tid + i * THREADS;
            int r = idx / BK, c = idx % BK;
            Bs[c][r] = Bp[r * K + k0 + c];
        }
        __syncthreads();
        #pragma unroll
        for (int k = 0; k < BK; k++) {
            float a[TM], bq[TN];
            #pragma unroll
            for (int i = 0; i < TM; i++) a[i] = As[k][ty * TM + i];
            #pragma unroll
            for (int j = 0; j < TN; j++) bq[j] = Bs[k][tx * TN + j];
            #pragma unroll
            for (int i = 0; i < TM; i++)
                #pragma unroll
                for (int j = 0; j < TN; j++)
                    acc[i][j] = fmaf(a[i], bq[j], acc[i][j]);
        }
        __syncthreads();
    }
    #pragma unroll
    for (int i = 0; i < TM; i++)
        #pragma unroll
        for (int j = 0; j < TN; j++)
            Cp[(size_t)(bm + ty * TM + i) * N + bn + tx * TN + j] = acc[i][j];
}

// ---------------- causal depthwise conv (k=4) + SiLU; also silu(z) ----------------
__global__ void conv_silu_kernel(const float* __restrict__ cw,
                                 const float* __restrict__ cb) {
    int bl = blockIdx.x;              // b*1024 + l
    int d  = threadIdx.x;             // 512 threads
    int l  = bl & 1023;
    float w0 = cw[d*4+0], w1 = cw[d*4+1], w2 = cw[d*4+2], w3 = cw[d*4+3];
    const float* base = g_xz + (size_t)(bl - l) * 1024 + d;   // start of this batch
    float acc = cb[d];
    acc = fmaf(w3, base[(size_t)l * 1024], acc);
    if (l >= 1) acc = fmaf(w2, base[(size_t)(l-1) * 1024], acc);
    if (l >= 2) acc = fmaf(w1, base[(size_t)(l-2) * 1024], acc);
    if (l >= 3) acc = fmaf(w0, base[(size_t)(l-3) * 1024], acc);
    float uu = acc * sigmoidf_(acc);
    g_u[(size_t)bl * kDI + d] = uu;
    float z = g_xz[(size_t)bl * 1024 + kDI + d];
    g_sz[(size_t)bl * kDI + d] = z * sigmoidf_(z);
}

// ---------------- dt = softplus(dbl[:, :16] @ W_dt^T + b_dt); extract Bs ----------------
__global__ void dt_kernel(const float* __restrict__ Wdt,
                          const float* __restrict__ bdt) {
    int m0 = blockIdx.x * 16;
    int tid = threadIdx.x;            // 256 threads
    __shared__ float s16[16][16];
    for (int i = tid; i < 16 * 80; i += 256) {
        int r = i / 80, c = i % 80;
        int idx = (m0 + r) * 80 + c;
        float v = 0.f;
        #pragma unroll
        for (int s = 0; s < kSlabs; s++) v += g_dbl[(size_t)s * kM * 80 + idx];
        if (c < 16) s16[r][c] = v;
        else        g_Bs[(size_t)(m0 + r) * kDS + (c - 16)] = v;
    }
    __syncthreads();
    #pragma unroll
    for (int dd = 0; dd < 2; dd++) {
        int d = tid + dd * 256;
        float w[16];
        const float4* wp = (const float4*)(Wdt + d * 16);
        #pragma unroll
        for (int q = 0; q < 4; q++) {
            float4 f = wp[q];
            w[4*q] = f.x; w[4*q+1] = f.y; w[4*q+2] = f.z; w[4*q+3] = f.w;
        }
        float bb = bdt[d];
        #pragma unroll 4
        for (int r = 0; r < 16; r++) {
            float acc = bb;
            #pragma unroll
            for (int q = 0; q < 16; q++) acc = fmaf(s16[r][q], w[q], acc);
            float o = (acc > 20.f) ? acc : log1pf(__expf(acc));
            g_dt[(size_t)(m0 + r) * kDI + d] = o;
        }
    }
}

// ---------------- selective scan ----------------
// One warp per (b, d) channel; lane j holds states n=2j, n=2j+1.
// Time loop unrolled x8; the 8 butterfly reductions are interleaved so the
// 26-cycle SHFL latency is hidden by 8-way ILP instead of serializing.
constexpr int kU = 8;
__global__ void __launch_bounds__(256)
scan_kernel(const float* __restrict__ C_SA,
            const float* __restrict__ A_log,
            const float* __restrict__ Dp) {
    int b    = blockIdx.y;
    int wid  = threadIdx.x >> 5;
    int lane = threadIdx.x & 31;
    int d    = blockIdx.x * 8 + wid;
    const float L2E = 1.4426950408889634f;
    float a0 = -__expf(A_log[d * kDS + 2 * lane])     * L2E;  // A*log2(e)
    float a1 = -__expf(A_log[d * kDS + 2 * lane + 1]) * L2E;
    float Dd = Dp[d];
    float h0 = 0.f, h1 = 0.f;

    const float*  dtp = g_dt + (size_t)b * kL * kDI + d;
    const float*  up  = g_u  + (size_t)b * kL * kDI + d;
    const float*  szp = g_sz + (size_t)b * kL * kDI + d;
    float*        yp  = g_y  + (size_t)b * kL * kDI + d;
    const float2* Bp  = (const float2*)(g_Bs + (size_t)b * kL * kDS) + lane;
    const float2* Cp  = (const float2*)(C_SA + (size_t)b * kL * kDS) + lane;

    for (int l0 = 0; l0 < kL; l0 += kU) {
        float p[kU], ud[kU];
        // recurrence for kU steps (loop-carried dep is just FMA lat 4)
        #pragma unroll
        for (int u = 0; u < kU; u++) {
            float  dt = __ldg(dtp + u * kDI);
            float  uu = __ldg(up  + u * kDI);
            float2 Bv = __ldg(Bp + u * 32);
            float2 Cv = __ldg(Cp + u * 32);
            float dA0 = ex2f(dt * a0);
            float dA1 = ex2f(dt * a1);
            float x = dt * uu;
            h0 = fmaf(dA0, h0, x * Bv.x);
            h1 = fmaf(dA1, h1, x * Bv.y);
            p[u]  = fmaf(h0, Cv.x, h1 * Cv.y);
            ud[u] = uu * Dd;
        }
        // interleaved butterfly reductions: 8-way ILP on SHFL
        #pragma unroll
        for (int o = 16; o > 0; o >>= 1) {
            #pragma unroll
            for (int u = 0; u < kU; u++)
                p[u] += __shfl_xor_sync(0xffffffffu, p[u], o);
        }
        if (lane == 0) {
            #pragma unroll
            for (int u = 0; u < kU; u++)
                yp[u * kDI] = (p[u] + ud[u]) * __ldg(szp + u * kDI);
        }
        dtp += kU * kDI; up += kU * kDI; szp += kU * kDI; yp += kU * kDI;
        Bp += kU * 32; Cp += kU * 32;
    }
}

// ---------------- launch ----------------
extern "C" void kernel_launch(void* const* d_in, const int* in_sizes, int n_in,
                              void* d_out, int out_size) {
    const float* x      = (const float*)d_in[0];
    const float* C_SA   = (const float*)d_in[1];
    const float* gamma  = (const float*)d_in[2];
    const float* beta   = (const float*)d_in[3];
    const float* W_in   = (const float*)d_in[4];
    const float* conv_w = (const float*)d_in[5];
    const float* conv_b = (const float*)d_in[6];
    const float* W_x    = (const float*)d_in[7];
    const float* W_dt   = (const float*)d_in[8];
    const float* b_dt   = (const float*)d_in[9];
    const float* A_log  = (const float*)d_in[10];
    const float* Dv     = (const float*)d_in[11];
    const float* W_out  = (const float*)d_in[12];
    float* out = (float*)d_out;

    float *p_xn, *p_xz, *p_u, *p_dbl, *p_y;
    cudaGetSymbolAddress((void**)&p_xn,  g_xn);
    cudaGetSymbolAddress((void**)&p_xz,  g_xz);
    cudaGetSymbolAddress((void**)&p_u,   g_u);
    cudaGetSymbolAddress((void**)&p_dbl, g_dbl);
    cudaGetSymbolAddress((void**)&p_y,   g_y);

    // 1. LayerNorm
    ln_kernel<<<kM, kDim>>>(x, gamma, beta);
    // 2. xz = xn @ W_in^T   (4096 x 1024 x 256)
    sgemm_nt<128, 64, 8, 8, 4><<<dim3(1024 / 64, kM / 128, 1), 256>>>(
        kM, 1024, kDim, kDim, p_xn, W_in, p_xz);
    // 3. causal conv + SiLU, plus silu(z)
    conv_silu_kernel<<<kM, kDI>>>(conv_w, conv_b);
    // 4. dbl = u @ W_x^T   (4096 x 80 x 512), split-K x8 into slabs
    sgemm_nt<64, 80, 16, 4, 5><<<dim3(1, kM / 64, kSlabs), 256>>>(
        kM, 80, kDI, kDI / kSlabs, p_u, W_x, p_dbl);
    // 5. dt = softplus(...), Bs extraction (sums slabs)
    dt_kernel<<<kM / 16, 256>>>(W_dt, b_dt);
    // 6. selective scan (fused + u*D, * silu(z))
    scan_kernel<<<dim3(kDI / 8, kB), 256>>>(C_SA, A_log, Dv);
    // 7. out = y @ W_out^T  (4096 x 256 x 512)
    sgemm_nt<128, 64, 8, 8, 4><<<dim3(kDim / 64, kM / 128, 1), 256>>>(
        kM, kDim, kDI, kDI, p_y, W_out, out);
}

// round 3
// speedup vs baseline: 1.2106x; 1.0545x over previous
#include <cuda_runtime.h>

// ---------------- problem constants ----------------
constexpr int kB   = 4;
constexpr int kL   = 1024;
constexpr int kDim = 256;
constexpr int kDI  = 512;   // d_inner
constexpr int kDS  = 64;    // d_state
constexpr int kM   = kB * kL;  // 4096 rows
constexpr int kSlabs = 8;      // split-K slabs for GEMM2

// ---------------- scratch (device globals; no allocs allowed) ----------------
__device__ float g_xn [kM * kDim];            // layernormed x
__device__ float g_xz [kM * 2 * kDI];         // [u_pre | z]
__device__ float g_u  [kM * kDI];             // conv+silu output
__device__ float g_sz [kM * kDI];             // silu(z), precomputed
__device__ float g_dbl[kSlabs * kM * 80];     // split-K slabs of u @ W_x^T
__device__ float g_dt [kM * kDI];             // softplus dt
__device__ float g_Bs [kM * kDS];             // B_t
__device__ float g_y  [kM * kDI];             // scan output (epilogue fused)
__device__ float g_o2 [2 * kM * kDim];        // split-K slabs of final GEMM

__device__ __forceinline__ float ex2f(float x) {
    float r; asm("ex2.approx.f32 %0, %1;" : "=f"(r) : "f"(x)); return r;
}
__device__ __forceinline__ float sigmoidf_(float x) {
    return 1.f / (1.f + __expf(-x));
}

// ---------------- nop (launch-slot shim so ncu captures GEMM1) ----------------
__global__ void nop_kernel() {}

// ---------------- LayerNorm: one block per row ----------------
__global__ void ln_kernel(const float* __restrict__ x,
                          const float* __restrict__ gamma,
                          const float* __restrict__ beta) {
    int row = blockIdx.x, t = threadIdx.x;           // 256 threads
    float v = x[row * kDim + t];
    float s = v, s2 = v * v;
    #pragma unroll
    for (int o = 16; o > 0; o >>= 1) {
        s  += __shfl_xor_sync(0xffffffffu, s,  o);
        s2 += __shfl_xor_sync(0xffffffffu, s2, o);
    }
    __shared__ float sh[16];
    if ((t & 31) == 0) { sh[t >> 5] = s; sh[8 + (t >> 5)] = s2; }
    __syncthreads();
    float ms = 0.f, ms2 = 0.f;
    #pragma unroll
    for (int i = 0; i < 8; i++) { ms += sh[i]; ms2 += sh[8 + i]; }
    float mu  = ms * (1.f / kDim);
    float var = ms2 * (1.f / kDim) - mu * mu;
    float r = rsqrtf(var + 1e-5f);
    g_xn[row * kDim + t] = (v - mu) * r * gamma[t] + beta[t];
}

// ---------------- double-buffered NT SGEMM: C = A[M,K] * B[N,K]^T ----------
// float4 global loads, BK=16, one __syncthreads per K-chunk, next chunk's
// LDG issued before the FMA block so memory latency hides under compute.
// Optional split-K via blockIdx.z (slab stride M*N).
template<int BM, int BN, int BK, int TM, int TN>
__global__ void __launch_bounds__((BM/TM)*(BN/TN))
sgemm_db(int M, int N, int K, int klen,
         const float* __restrict__ A, const float* __restrict__ B,
         float* __restrict__ C) {
    constexpr int THREADS = (BM / TM) * (BN / TN);        // 256
    constexpr int A_F4 = BM * BK / 4 / THREADS;           // 2
    constexpr int B_F4 = BN * BK / 4 / THREADS;           // 1
    __shared__ float As[2][BK][BM];
    __shared__ float Bs[2][BK][BN];
    int tid = threadIdx.x;
    int bn = blockIdx.x * BN;
    int bm = blockIdx.y * BM;
    int kz = blockIdx.z;
    const float* Ap = A + (size_t)bm * K + (size_t)kz * klen;
    const float* Bp = B + (size_t)bn * K + (size_t)kz * klen;
    float* Cp = C + (size_t)kz * M * N;

    int tx = tid % (BN / TN);
    int ty = tid / (BN / TN);

    // per-thread global-load coordinates (row, 4-col group within BK)
    int ar[A_F4], ac[A_F4];
    #pragma unroll
    for (int i = 0; i < A_F4; i++) {
        int f = tid + i * THREADS;
        ar[i] = f / (BK / 4); ac[i] = (f % (BK / 4)) * 4;
    }
    int br[B_F4], bc[B_F4];
    #pragma unroll
    for (int i = 0; i < B_F4; i++) {
        int f = tid + i * THREADS;
        br[i] = f / (BK / 4); bc[i] = (f % (BK / 4)) * 4;
    }

    float acc[TM][TN];
    #pragma unroll
    for (int i = 0; i < TM; i++)
        #pragma unroll
        for (int j = 0; j < TN; j++) acc[i][j] = 0.f;

    float4 ra[A_F4], rb[B_F4];
    const int nk = klen / BK;

    // prologue: chunk 0 -> regs -> smem buf 0
    #pragma unroll
    for (int i = 0; i < A_F4; i++)
        ra[i] = *(const float4*)(Ap + (size_t)ar[i] * K + ac[i]);
    #pragma unroll
    for (int i = 0; i < B_F4; i++)
        rb[i] = *(const float4*)(Bp + (size_t)br[i] * K + bc[i]);
    #pragma unroll
    for (int i = 0; i < A_F4; i++) {
        As[0][ac[i] + 0][ar[i]] = ra[i].x; As[0][ac[i] + 1][ar[i]] = ra[i].y;
        As[0][ac[i] + 2][ar[i]] = ra[i].z; As[0][ac[i] + 3][ar[i]] = ra[i].w;
    }
    #pragma unroll
    for (int i = 0; i < B_F4; i++) {
        Bs[0][bc[i] + 0][br[i]] = rb[i].x; Bs[0][bc[i] + 1][br[i]] = rb[i].y;
        Bs[0][bc[i] + 2][br[i]] = rb[i].z; Bs[0][bc[i] + 3][br[i]] = rb[i].w;
    }
    __syncthreads();

    for (int c = 0; c < nk; c++) {
        int buf = c & 1;
        if (c + 1 < nk) {
            int k1 = (c + 1) * BK;
            #pragma unroll
            for (int i = 0; i < A_F4; i++)
                ra[i] = *(const float4*)(Ap + (size_t)ar[i] * K + k1 + ac[i]);
            #pragma unroll
            for (int i = 0; i < B_F4; i++)
                rb[i] = *(const float4*)(Bp + (size_t)br[i] * K + k1 + bc[i]);
        }
        #pragma unroll
        for (int k = 0; k < BK; k++) {
            float a[TM], b[TN];
            const float4* av = (const float4*)&As[buf][k][ty * TM];
            const float4* bv = (const float4*)&Bs[buf][k][tx * TN];
            #pragma unroll
            for (int q = 0; q < TM / 4; q++) {
                float4 t = av[q];
                a[4*q] = t.x; a[4*q+1] = t.y; a[4*q+2] = t.z; a[4*q+3] = t.w;
            }
            #pragma unroll
            for (int q = 0; q < TN / 4; q++) {
                float4 t = bv[q];
                b[4*q] = t.x; b[4*q+1] = t.y; b[4*q+2] = t.z; b[4*q+3] = t.w;
            }
            #pragma unroll
            for (int i = 0; i < TM; i++)
                #pragma unroll
                for (int j = 0; j < TN; j++)
                    acc[i][j] = fmaf(a[i], b[j], acc[i][j]);
        }
        if (c + 1 < nk) {
            int nb = buf ^ 1;
            #pragma unroll
            for (int i = 0; i < A_F4; i++) {
                As[nb][ac[i] + 0][ar[i]] = ra[i].x; As[nb][ac[i] + 1][ar[i]] = ra[i].y;
                As[nb][ac[i] + 2][ar[i]] = ra[i].z; As[nb][ac[i] + 3][ar[i]] = ra[i].w;
            }
            #pragma unroll
            for (int i = 0; i < B_F4; i++) {
                Bs[nb][bc[i] + 0][br[i]] = rb[i].x; Bs[nb][bc[i] + 1][br[i]] = rb[i].y;
                Bs[nb][bc[i] + 2][br[i]] = rb[i].z; Bs[nb][bc[i] + 3][br[i]] = rb[i].w;
            }
        }
        __syncthreads();
    }

    #pragma unroll
    for (int i = 0; i < TM; i++)
        #pragma unroll
        for (int j = 0; j < TN / 4; j++) {
            float4 v = make_float4(acc[i][4*j], acc[i][4*j+1],
                                   acc[i][4*j+2], acc[i][4*j+3]);
            *(float4*)(Cp + (size_t)(bm + ty * TM + i) * N + bn + tx * TN + 4*j) = v;
        }
}

// ---------------- small NT SGEMM (GEMM2 only, N=80) ----------------
template<int BM, int BN, int BK, int TM, int TN>
__global__ void __launch_bounds__((BM/TM)*(BN/TN))
sgemm_nt(int M, int N, int K, int klen,
         const float* __restrict__ A, const float* __restrict__ B,
         float* __restrict__ Cout) {
    constexpr int THREADS = (BM / TM) * (BN / TN);
    __shared__ float As[BK][BM];
    __shared__ float Bs[BK][BN];
    int tid = threadIdx.x;
    int bn = blockIdx.x * BN;
    int bm = blockIdx.y * BM;
    int kz = blockIdx.z;
    const float* Ap = A + (size_t)bm * K + kz * klen;
    const float* Bp = B + (size_t)bn * K + kz * klen;
    float* Cp = Cout + (size_t)kz * M * N;

    float acc[TM][TN];
    #pragma unroll
    for (int i = 0; i < TM; i++)
        #pragma unroll
        for (int j = 0; j < TN; j++) acc[i][j] = 0.f;

    int tx = tid % (BN / TN);
    int ty = tid / (BN / TN);

    for (int k0 = 0; k0 < klen; k0 += BK) {
        #pragma unroll
        for (int i = 0; i < BM * BK / THREADS; i++) {
            int idx = tid + i * THREADS;
            int r = idx / BK, c = idx % BK;
            As[c][r] = Ap[r * K + k0 + c];
        }
        #pragma unroll
        for (int i = 0; i < BN * BK / THREADS; i++) {
            int idx = tid + i * THREADS;
            int r = idx / BK, c = idx % BK;
            Bs[c][r] = Bp[r * K + k0 + c];
        }
        __syncthreads();
        #pragma unroll
        for (int k = 0; k < BK; k++) {
            float a[TM], bq[TN];
            #pragma unroll
            for (int i = 0; i < TM; i++) a[i] = As[k][ty * TM + i];
            #pragma unroll
            for (int j = 0; j < TN; j++) bq[j] = Bs[k][tx * TN + j];
            #pragma unroll
            for (int i = 0; i < TM; i++)
                #pragma unroll
                for (int j = 0; j < TN; j++)
                    acc[i][j] = fmaf(a[i], bq[j], acc[i][j]);
        }
        __syncthreads();
    }
    #pragma unroll
    for (int i = 0; i < TM; i++)
        #pragma unroll
        for (int j = 0; j < TN; j++)
            Cp[(size_t)(bm + ty * TM + i) * N + bn + tx * TN + j] = acc[i][j];
}

// ---------------- causal depthwise conv (k=4) + SiLU; also silu(z) ----------------
__global__ void conv_silu_kernel(const float* __restrict__ cw,
                                 const float* __restrict__ cb) {
    int bl = blockIdx.x;              // b*1024 + l
    int d  = threadIdx.x;             // 512 threads
    int l  = bl & 1023;
    float w0 = cw[d*4+0], w1 = cw[d*4+1], w2 = cw[d*4+2], w3 = cw[d*4+3];
    const float* base = g_xz + (size_t)(bl - l) * 1024 + d;   // start of this batch
    float acc = cb[d];
    acc = fmaf(w3, base[(size_t)l * 1024], acc);
    if (l >= 1) acc = fmaf(w2, base[(size_t)(l-1) * 1024], acc);
    if (l >= 2) acc = fmaf(w1, base[(size_t)(l-2) * 1024], acc);
    if (l >= 3) acc = fmaf(w0, base[(size_t)(l-3) * 1024], acc);
    float uu = acc * sigmoidf_(acc);
    g_u[(size_t)bl * kDI + d] = uu;
    float z = g_xz[(size_t)bl * 1024 + kDI + d];
    g_sz[(size_t)bl * kDI + d] = z * sigmoidf_(z);
}

// ---------------- dt = softplus(dbl[:, :16] @ W_dt^T + b_dt); extract Bs ----------------
__global__ void dt_kernel(const float* __restrict__ Wdt,
                          const float* __restrict__ bdt) {
    int m0 = blockIdx.x * 16;
    int tid = threadIdx.x;            // 256 threads
    __shared__ float s16[16][16];
    for (int i = tid; i < 16 * 80; i += 256) {
        int r = i / 80, c = i % 80;
        int idx = (m0 + r) * 80 + c;
        float v = 0.f;
        #pragma unroll
        for (int s = 0; s < kSlabs; s++) v += g_dbl[(size_t)s * kM * 80 + idx];
        if (c < 16) s16[r][c] = v;
        else        g_Bs[(size_t)(m0 + r) * kDS + (c - 16)] = v;
    }
    __syncthreads();
    #pragma unroll
    for (int dd = 0; dd < 2; dd++) {
        int d = tid + dd * 256;
        float w[16];
        const float4* wp = (const float4*)(Wdt + d * 16);
        #pragma unroll
        for (int q = 0; q < 4; q++) {
            float4 f = wp[q];
            w[4*q] = f.x; w[4*q+1] = f.y; w[4*q+2] = f.z; w[4*q+3] = f.w;
        }
        float bb = bdt[d];
        #pragma unroll 4
        for (int r = 0; r < 16; r++) {
            float acc = bb;
            #pragma unroll
            for (int q = 0; q < 16; q++) acc = fmaf(s16[r][q], w[q], acc);
            float o = (acc > 20.f) ? acc : log1pf(__expf(acc));
            g_dt[(size_t)(m0 + r) * kDI + d] = o;
        }
    }
}

// ---------------- selective scan ----------------
constexpr int kU = 8;
__global__ void __launch_bounds__(256)
scan_kernel(const float* __restrict__ C_SA,
            const float* __restrict__ A_log,
            const float* __restrict__ Dp) {
    int b    = blockIdx.y;
    int wid  = threadIdx.x >> 5;
    int lane = threadIdx.x & 31;
    int d    = blockIdx.x * 8 + wid;
    const float L2E = 1.4426950408889634f;
    float a0 = -__expf(A_log[d * kDS + 2 * lane])     * L2E;  // A*log2(e)
    float a1 = -__expf(A_log[d * kDS + 2 * lane + 1]) * L2E;
    float Dd = Dp[d];
    float h0 = 0.f, h1 = 0.f;

    const float*  dtp = g_dt + (size_t)b * kL * kDI + d;
    const float*  up  = g_u  + (size_t)b * kL * kDI + d;
    const float*  szp = g_sz + (size_t)b * kL * kDI + d;
    float*        yp  = g_y  + (size_t)b * kL * kDI + d;
    const float2* Bp  = (const float2*)(g_Bs + (size_t)b * kL * kDS) + lane;
    const float2* Cp  = (const float2*)(C_SA + (size_t)b * kL * kDS) + lane;

    for (int l0 = 0; l0 < kL; l0 += kU) {
        float p[kU], ud[kU];
        #pragma unroll
        for (int u = 0; u < kU; u++) {
            float  dt = __ldg(dtp + u * kDI);
            float  uu = __ldg(up  + u * kDI);
            float2 Bv = __ldg(Bp + u * 32);
            float2 Cv = __ldg(Cp + u * 32);
            float dA0 = ex2f(dt * a0);
            float dA1 = ex2f(dt * a1);
            float x = dt * uu;
            h0 = fmaf(dA0, h0, x * Bv.x);
            h1 = fmaf(dA1, h1, x * Bv.y);
            p[u]  = fmaf(h0, Cv.x, h1 * Cv.y);
            ud[u] = uu * Dd;
        }
        #pragma unroll
        for (int o = 16; o > 0; o >>= 1) {
            #pragma unroll
            for (int u = 0; u < kU; u++)
                p[u] += __shfl_xor_sync(0xffffffffu, p[u], o);
        }
        if (lane == 0) {
            #pragma unroll
            for (int u = 0; u < kU; u++)
                yp[u * kDI] = (p[u] + ud[u]) * __ldg(szp + u * kDI);
        }
        dtp += kU * kDI; up += kU * kDI; szp += kU * kDI; yp += kU * kDI;
        Bp += kU * 32; Cp += kU * 32;
    }
}

// ---------------- sum the two split-K slabs of the final GEMM ----------------
__global__ void addslabs_kernel(float* __restrict__ out) {
    int i = blockIdx.x * blockDim.x + threadIdx.x;
    const float4* s0 = (const float4*)g_o2;
    const float4* s1 = (const float4*)(g_o2 + (size_t)kM * kDim);
    float4 a = s0[i], b = s1[i];
    ((float4*)out)[i] = make_float4(a.x + b.x, a.y + b.y, a.z + b.z, a.w + b.w);
}

// ---------------- launch ----------------
extern "C" void kernel_launch(void* const* d_in, const int* in_sizes, int n_in,
                              void* d_out, int out_size) {
    const float* x      = (const float*)d_in[0];
    const float* C_SA   = (const float*)d_in[1];
    const float* gamma  = (const float*)d_in[2];
    const float* beta   = (const float*)d_in[3];
    const float* W_in   = (const float*)d_in[4];
    const float* conv_w = (const float*)d_in[5];
    const float* conv_b = (const float*)d_in[6];
    const float* W_x    = (const float*)d_in[7];
    const float* W_dt   = (const float*)d_in[8];
    const float* b_dt   = (const float*)d_in[9];
    const float* A_log  = (const float*)d_in[10];
    const float* Dv     = (const float*)d_in[11];
    const float* W_out  = (const float*)d_in[12];
    float* out = (float*)d_out;

    float *p_xn, *p_xz, *p_u, *p_dbl, *p_y, *p_o2;
    cudaGetSymbolAddress((void**)&p_xn,  g_xn);
    cudaGetSymbolAddress((void**)&p_xz,  g_xz);
    cudaGetSymbolAddress((void**)&p_u,   g_u);
    cudaGetSymbolAddress((void**)&p_dbl, g_dbl);
    cudaGetSymbolAddress((void**)&p_y,   g_y);
    cudaGetSymbolAddress((void**)&p_o2,  g_o2);

    // 1. LayerNorm
    ln_kernel<<<kM, kDim>>>(x, gamma, beta);
    // 2-3. nop shims so ncu's fixed capture slot lands on GEMM1
    nop_kernel<<<1, 32>>>();
    nop_kernel<<<1, 32>>>();
    // 4. xz = xn @ W_in^T   (4096 x 1024 x 256)
    sgemm_db<128, 64, 16, 8, 4><<<dim3(1024 / 64, kM / 128, 1), 256>>>(
        kM, 1024, kDim, kDim, p_xn, W_in, p_xz);
    // 5. causal conv + SiLU, plus silu(z)
    conv_silu_kernel<<<kM, kDI>>>(conv_w, conv_b);
    // 6. dbl = u @ W_x^T   (4096 x 80 x 512), split-K x8 into slabs
    sgemm_nt<64, 80, 16, 4, 5><<<dim3(1, kM / 64, kSlabs), 256>>>(
        kM, 80, kDI, kDI / kSlabs, p_u, W_x, p_dbl);
    // 7. dt = softplus(...), Bs extraction (sums slabs)
    dt_kernel<<<kM / 16, 256>>>(W_dt, b_dt);
    // 8. selective scan (fused + u*D, * silu(z))
    scan_kernel<<<dim3(kDI / 8, kB), 256>>>(C_SA, A_log, Dv);
    // 9. out_slabs = y @ W_out^T  (4096 x 256 x 512), split-K x2
    sgemm_db<128, 64, 16, 8, 4><<<dim3(kDim / 64, kM / 128, 2), 256>>>(
        kM, kDim, kDI, kDI / 2, p_y, W_out, p_o2);
    // 10. out = slab0 + slab1
    addslabs_kernel<<<kM * kDim / 4 / 256, 256>>>(out);
}